// round 1
// baseline (speedup 1.0000x reference)
#include <cuda_runtime.h>
#include <cstdint>

// GRU: B=128, T=4096, I=6, H=32, O=2
// One CTA per sequence. 4 warps:
//   warp 0: recurrence (critical path). lane k owns hidden unit k, all 3 gates.
//   warps 1,3: produce gx[t] = x[t]@w_ih^T + b_ih into smem ring, one chunk ahead.
//   warp 2: consume h history ring -> out[t] = fc_w@h + fc_b, one chunk behind.
// Chunked double-buffer pipeline, one __syncthreads per 32-step chunk.

#define Bq 128
#define Tq 4096
#define Iq 6
#define Hq 32
#define Gq 96
#define Oq 2
#define CH 32
#define NCH (Tq / CH)
#define HPAD 34   // pad h rows to 34 floats: 8B-aligned rows, <=2-way LDS conflicts for warp2

typedef unsigned long long u64;

__device__ __forceinline__ float ex2a(float x) { float y; asm("ex2.approx.f32 %0, %1;" : "=f"(y) : "f"(x)); return y; }
__device__ __forceinline__ float rcpa(float x) { float y; asm("rcp.approx.f32 %0, %1;" : "=f"(y) : "f"(x)); return y; }
// sigmoid(x) = 1/(1+e^-x); safe at extremes (rcp(inf)=0)
__device__ __forceinline__ float sigm(float x) { return rcpa(1.0f + ex2a(-1.4426950408889634f * x)); }
// tanh(x) = 1 - 2/(e^{2x}+1); safe at extremes
__device__ __forceinline__ float tanha(float x) { return 1.0f - 2.0f * rcpa(1.0f + ex2a(2.8853900817779268f * x)); }

__device__ __forceinline__ u64 pk2(float lo, float hi) { u64 r; asm("mov.b64 %0, {%1, %2};" : "=l"(r) : "f"(lo), "f"(hi)); return r; }
__device__ __forceinline__ void upk2(u64 v, float& lo, float& hi) { asm("mov.b64 {%0, %1}, %2;" : "=f"(lo), "=f"(hi) : "l"(v)); }
__device__ __forceinline__ u64 f2fma(u64 a, u64 b, u64 c) { u64 d; asm("fma.rn.f32x2 %0, %1, %2, %3;" : "=l"(d) : "l"(a), "l"(b), "l"(c)); return d; }
__device__ __forceinline__ u64 f2add(u64 a, u64 b) { u64 d; asm("add.rn.f32x2 %0, %1, %2;" : "=l"(d) : "l"(a), "l"(b)); return d; }
__device__ __forceinline__ uint32_t saddr(const void* p) {
    uint32_t a;
    asm("{ .reg .u64 t; cvta.to.shared.u64 t, %1; cvt.u32.u64 %0, t; }" : "=r"(a) : "l"(p));
    return a;
}
__device__ __forceinline__ u64 lds64v(uint32_t a) { u64 v; asm volatile("ld.shared.b64 %0, [%1];" : "=l"(v) : "r"(a)); return v; }
__device__ __forceinline__ void sts32v(uint32_t a, float v) { asm volatile("st.shared.f32 [%0], %1;" :: "r"(a), "f"(v)); }

__global__ void __launch_bounds__(128, 1) gru_seq_kernel(
    const float* __restrict__ x,        // [B, T, I]
    const int*   __restrict__ lengths,  // [B]
    const float* __restrict__ w_ih,     // [3H, I]
    const float* __restrict__ w_hh,     // [3H, H]
    const float* __restrict__ b_ih,     // [3H]
    const float* __restrict__ b_hh,     // [3H]
    const float* __restrict__ fc_w,     // [O, H]
    const float* __restrict__ fc_b,     // [O]
    float* __restrict__ out)            // [B, T, O]
{
    __shared__ __align__(16) float s_gx[2][CH][Gq];   // gx ring (producers -> warp0)
    __shared__ __align__(16) float s_h[2][CH][HPAD];  // h history ring (warp0 -> warp2), also h broadcast

    const int lane = threadIdx.x & 31;
    const int warp = threadIdx.x >> 5;
    const int b = blockIdx.x;
    const int L = lengths[b];

    // ---- warp-0 persistent state (recurrent weights, packed f32x2) ----
    u64 wr[16], wz[16], wn[16];
    float bhr = 0.f, bhz = 0.f, bhn = 0.f;
    float hk = 0.f;
    uint32_t hbase = saddr(&s_h[0][0][0]);
    uint32_t gxbase = saddr(&s_gx[0][0][0]);
    uint32_t hprev = hbase + ((1 * CH + (CH - 1)) * HPAD) * 4;  // zero row

    // ---- producer persistent state ----
    float wiA[Iq], wiB[Iq], wiC[Iq];
    float biA = 0.f, biB = 0.f, biC = 0.f;

    if (warp == 0) {
        const float* rr = w_hh + lane * Hq;
        const float* rz = w_hh + (Hq + lane) * Hq;
        const float* rn = w_hh + (2 * Hq + lane) * Hq;
#pragma unroll
        for (int j = 0; j < 16; j++) {
            wr[j] = pk2(rr[2 * j], rr[2 * j + 1]);
            wz[j] = pk2(rz[2 * j], rz[2 * j + 1]);
            wn[j] = pk2(rn[2 * j], rn[2 * j + 1]);
        }
        bhr = b_hh[lane];
        bhz = b_hh[Hq + lane];
        bhn = b_hh[2 * Hq + lane];
        s_h[1][CH - 1][lane] = 0.0f;  // initial hidden state row
    } else if (warp == 1 || warp == 3) {
#pragma unroll
        for (int i = 0; i < Iq; i++) {
            wiA[i] = w_ih[lane * Iq + i];
            wiB[i] = w_ih[(Hq + lane) * Iq + i];
            wiC[i] = w_ih[(2 * Hq + lane) * Iq + i];
        }
        biA = b_ih[lane];
        biB = b_ih[Hq + lane];
        biC = b_ih[2 * Hq + lane];
        // ---- prologue: produce gx for chunk 0 ----
        {
            const int s0 = (warp == 3) ? (CH / 2) : 0;
            const float* xp = x + ((size_t)b * Tq + s0) * Iq;
            float* g = &s_gx[0][s0][0];
#pragma unroll 1
            for (int s = 0; s < CH / 2; s++) {
                float xv[Iq];
#pragma unroll
                for (int i = 0; i < Iq; i++) xv[i] = xp[i];
                float gr = biA, gz = biB, gn = biC;
#pragma unroll
                for (int i = 0; i < Iq; i++) {
                    gr = fmaf(wiA[i], xv[i], gr);
                    gz = fmaf(wiB[i], xv[i], gz);
                    gn = fmaf(wiC[i], xv[i], gn);
                }
                g[lane] = gr;
                g[Hq + lane] = gz;
                g[2 * Hq + lane] = gn;
                g += Gq;
                xp += Iq;
            }
        }
    }

    // ================= main chunk pipeline =================
    for (int c = 0; c < NCH; c++) {
        __syncthreads();

        if (warp == 0) {
            // -------- recurrence for chunk c --------
            int nst = L - c * CH;
            if (nst > CH) nst = CH;
            uint32_t gxa = gxbase + ((c & 1) * CH * Gq + lane) * 4;
            uint32_t hrow = hbase + ((c & 1) * CH * HPAD) * 4;
#pragma unroll 1
            for (int s = 0; s < nst; s++) {
                // broadcast-load full h (16 x f32x2)
                u64 hp[16];
#pragma unroll
                for (int j = 0; j < 16; j++) hp[j] = lds64v(hprev + 8 * j);
                float gxr = s_gx[c & 1][s][lane];
                float gxz = s_gx[c & 1][s][Hq + lane];
                float gxn = s_gx[c & 1][s][2 * Hq + lane];
                (void)gxa;
                // three 32-MAC dots as packed f32x2 (2 accumulators each)
                u64 a0 = 0ull, a1 = 0ull, z0 = 0ull, z1 = 0ull, n0 = 0ull, n1 = 0ull;
#pragma unroll
                for (int j = 0; j < 16; j += 2) {
                    a0 = f2fma(wr[j], hp[j], a0);
                    a1 = f2fma(wr[j + 1], hp[j + 1], a1);
                    z0 = f2fma(wz[j], hp[j], z0);
                    z1 = f2fma(wz[j + 1], hp[j + 1], z1);
                    n0 = f2fma(wn[j], hp[j], n0);
                    n1 = f2fma(wn[j + 1], hp[j + 1], n1);
                }
                float lo, hi;
                upk2(f2add(a0, a1), lo, hi);
                float rin = (gxr + bhr) + (lo + hi);
                upk2(f2add(z0, z1), lo, hi);
                float zin = (gxz + bhz) + (lo + hi);
                upk2(f2add(n0, n1), lo, hi);
                float nin = bhn + (lo + hi);        // hn (includes b_hh_n)

                float r = sigm(rin);
                float z = sigm(zin);
                float aa = fmaf(r, nin, gxn);        // xn + r*hn
                float nv = tanha(aa);
                hk = fmaf(z, hk - nv, nv);           // (1-z)*n + z*h

                sts32v(hrow + lane * 4, hk);
                hprev = hrow;
                __syncwarp();
                hrow += HPAD * 4;
            }
        } else if (warp == 2) {
            // -------- FC output for chunk c-1 --------
            if (c > 0) {
                const int cp = c - 1;
                const int t = cp * CH + lane;
                float o0 = __ldg(fc_b + 0);
                float o1 = __ldg(fc_b + 1);
                if (t < L) {
                    const float* hr = &s_h[cp & 1][lane][0];
#pragma unroll
                    for (int j = 0; j < Hq; j++) {
                        float hv = hr[j];
                        o0 = fmaf(__ldg(fc_w + j), hv, o0);
                        o1 = fmaf(__ldg(fc_w + Hq + j), hv, o1);
                    }
                }
                float2 v = make_float2(o0, o1);
                *reinterpret_cast<float2*>(out + ((size_t)b * Tq + t) * Oq) = v;
            }
        } else {
            // -------- produce gx for chunk c+1 --------
            const int cc = c + 1;
            if (cc < NCH) {
                const int s0 = (warp == 3) ? (CH / 2) : 0;
                const float* xp = x + ((size_t)b * Tq + cc * CH + s0) * Iq;
                float* g = &s_gx[cc & 1][s0][0];
#pragma unroll 1
                for (int s = 0; s < CH / 2; s++) {
                    float xv[Iq];
#pragma unroll
                    for (int i = 0; i < Iq; i++) xv[i] = xp[i];
                    float gr = biA, gz = biB, gn = biC;
#pragma unroll
                    for (int i = 0; i < Iq; i++) {
                        gr = fmaf(wiA[i], xv[i], gr);
                        gz = fmaf(wiB[i], xv[i], gz);
                        gn = fmaf(wiC[i], xv[i], gn);
                    }
                    g[lane] = gr;
                    g[Hq + lane] = gz;
                    g[2 * Hq + lane] = gn;
                    g += Gq;
                    xp += Iq;
                }
            }
        }
    }

    // ---- epilogue: output last chunk ----
    __syncthreads();
    if (warp == 2) {
        const int cp = NCH - 1;
        const int t = cp * CH + lane;
        float o0 = __ldg(fc_b + 0);
        float o1 = __ldg(fc_b + 1);
        if (t < L) {
            const float* hr = &s_h[cp & 1][lane][0];
#pragma unroll
            for (int j = 0; j < Hq; j++) {
                float hv = hr[j];
                o0 = fmaf(__ldg(fc_w + j), hv, o0);
                o1 = fmaf(__ldg(fc_w + Hq + j), hv, o1);
            }
        }
        float2 v = make_float2(o0, o1);
        *reinterpret_cast<float2*>(out + ((size_t)b * Tq + t) * Oq) = v;
    }
}

extern "C" void kernel_launch(void* const* d_in, const int* in_sizes, int n_in,
                              void* d_out, int out_size) {
    const float* x       = (const float*)d_in[0];
    const int*   lengths = (const int*)d_in[1];
    const float* w_ih    = (const float*)d_in[2];
    const float* w_hh    = (const float*)d_in[3];
    const float* b_ih    = (const float*)d_in[4];
    const float* b_hh    = (const float*)d_in[5];
    const float* fc_w    = (const float*)d_in[6];
    const float* fc_b    = (const float*)d_in[7];
    float* out = (float*)d_out;

    gru_seq_kernel<<<Bq, 128>>>(x, lengths, w_ih, w_hh, b_ih, b_hh, fc_w, fc_b, out);
}

// round 2
// speedup vs baseline: 1.0761x; 1.0761x over previous
#include <cuda_runtime.h>
#include <cstdint>

// GRU: B=128, T=4096, I=6, H=32, O=2
// One CTA per sequence. 4 warps:
//   warp 0: recurrence (critical path). lane k owns hidden unit k, all 3 gates.
//   warps 1,3: produce pre-scaled gate inputs into smem ring, one chunk ahead.
//   warp 2: consume h history ring -> out[t] = fc_w@h + fc_b, one chunk behind.
// All activation-function constant multiplies and bias adds are folded into
// the weights / producer outputs so the per-step dependency chain is:
//   sync -> LDS(h) -> 4-deep f2fma -> tree-add -> ex2 -> add -> rcp (=r)
//        -> fma -> ex2 -> add -> rcp (=q_n) -> fma (=h_new) -> STS

#define Bq 128
#define Tq 4096
#define Iq 6
#define Hq 32
#define Gq 96
#define Oq 2
#define CH 32
#define NCH (Tq / CH)
#define HPAD 36   // 144B rows: 16B-aligned for ld.shared.v2.b64

#define KRf (-1.4426950408889634f)   // -log2(e): sigmoid(v)=rcp(1+ex2(KR*v))
#define KNf ( 2.8853900817779268f)   // 2*log2(e): tanh(v)=1-2*rcp(1+ex2(KN*v))

typedef unsigned long long u64;

__device__ __forceinline__ float ex2a(float x) { float y; asm("ex2.approx.f32 %0, %1;" : "=f"(y) : "f"(x)); return y; }
__device__ __forceinline__ float rcpa(float x) { float y; asm("rcp.approx.f32 %0, %1;" : "=f"(y) : "f"(x)); return y; }

__device__ __forceinline__ u64 pk2(float lo, float hi) { u64 r; asm("mov.b64 %0, {%1, %2};" : "=l"(r) : "f"(lo), "f"(hi)); return r; }
__device__ __forceinline__ void upk2(u64 v, float& lo, float& hi) { asm("mov.b64 {%0, %1}, %2;" : "=f"(lo), "=f"(hi) : "l"(v)); }
__device__ __forceinline__ u64 f2fma(u64 a, u64 b, u64 c) { u64 d; asm("fma.rn.f32x2 %0, %1, %2, %3;" : "=l"(d) : "l"(a), "l"(b), "l"(c)); return d; }
__device__ __forceinline__ u64 f2add(u64 a, u64 b) { u64 d; asm("add.rn.f32x2 %0, %1, %2;" : "=l"(d) : "l"(a), "l"(b)); return d; }
__device__ __forceinline__ uint32_t saddr(const void* p) {
    uint32_t a;
    asm("{ .reg .u64 t; cvta.to.shared.u64 t, %1; cvt.u32.u64 %0, t; }" : "=r"(a) : "l"(p));
    return a;
}
__device__ __forceinline__ void lds128v(uint32_t a, u64& v0, u64& v1) {
    asm volatile("ld.shared.v2.b64 {%0, %1}, [%2];" : "=l"(v0), "=l"(v1) : "r"(a));
}
__device__ __forceinline__ float lds32v(uint32_t a) { float v; asm volatile("ld.shared.f32 %0, [%1];" : "=f"(v) : "r"(a)); return v; }
__device__ __forceinline__ void sts32v(uint32_t a, float v) { asm volatile("st.shared.f32 [%0], %1;" :: "r"(a), "f"(v)); }

// horizontal sum of 4 packed-f32x2 accumulators
__device__ __forceinline__ float hsum4(u64 a0, u64 a1, u64 a2, u64 a3) {
    u64 s = f2add(f2add(a0, a1), f2add(a2, a3));
    float lo, hi; upk2(s, lo, hi);
    return lo + hi;
}

__global__ void __launch_bounds__(128, 1) gru_seq_kernel(
    const float* __restrict__ x,        // [B, T, I]
    const int*   __restrict__ lengths,  // [B]
    const float* __restrict__ w_ih,     // [3H, I]
    const float* __restrict__ w_hh,     // [3H, H]
    const float* __restrict__ b_ih,     // [3H]
    const float* __restrict__ b_hh,     // [3H]
    const float* __restrict__ fc_w,     // [O, H]
    const float* __restrict__ fc_b,     // [O]
    float* __restrict__ out)            // [B, T, O]
{
    __shared__ __align__(16) float s_gx[2][CH][Gq];   // pre-scaled gate-x ring
    __shared__ __align__(16) float s_h[2][CH][HPAD];  // h ring (warp0 -> warp2), also h broadcast

    const int lane = threadIdx.x & 31;
    const int warp = threadIdx.x >> 5;
    const int b = blockIdx.x;
    const int L = lengths[b];

    // ---- warp-0 persistent state (pre-scaled recurrent weights, packed f32x2) ----
    u64 wr[16], wz[16], wn[16];
    u64 bhn_pk = 0ull;
    float hk = 0.f;
    uint32_t hbase = saddr(&s_h[0][0][0]);
    uint32_t gxbase = saddr(&s_gx[0][0][0]);
    uint32_t hprev = hbase + ((1 * CH + (CH - 1)) * HPAD) * 4;  // zero row

    // ---- producer persistent state ----
    float wiA[Iq], wiB[Iq], wiC[Iq];
    float biA = 0.f, biB = 0.f, biC = 0.f;   // pre-combined biases

    if (warp == 0) {
        const float* rr = w_hh + lane * Hq;
        const float* rz = w_hh + (Hq + lane) * Hq;
        const float* rn = w_hh + (2 * Hq + lane) * Hq;
#pragma unroll
        for (int j = 0; j < 16; j++) {
            wr[j] = pk2(KRf * rr[2 * j], KRf * rr[2 * j + 1]);
            wz[j] = pk2(KRf * rz[2 * j], KRf * rz[2 * j + 1]);
            wn[j] = pk2(KNf * rn[2 * j], KNf * rn[2 * j + 1]);
        }
        bhn_pk = pk2(KNf * b_hh[2 * Hq + lane], 0.0f);
        s_h[1][CH - 1][lane] = 0.0f;  // initial hidden state row
    } else if (warp == 1 || warp == 3) {
#pragma unroll
        for (int i = 0; i < Iq; i++) {
            wiA[i] = w_ih[lane * Iq + i];
            wiB[i] = w_ih[(Hq + lane) * Iq + i];
            wiC[i] = w_ih[(2 * Hq + lane) * Iq + i];
        }
        // producer outputs are pre-scaled: r,z get KR*(gx+b_hh), n gets KN*gx
        biA = b_ih[lane] + b_hh[lane];
        biB = b_ih[Hq + lane] + b_hh[Hq + lane];
        biC = b_ih[2 * Hq + lane];
        // ---- prologue: produce chunk 0 ----
        {
            const int s0 = (warp == 3) ? (CH / 2) : 0;
            const float* xp = x + ((size_t)b * Tq + s0) * Iq;
            float* g = &s_gx[0][s0][0];
#pragma unroll 1
            for (int s = 0; s < CH / 2; s++) {
                float xv[Iq];
#pragma unroll
                for (int i = 0; i < Iq; i++) xv[i] = xp[i];
                float gr = biA, gz = biB, gn = biC;
#pragma unroll
                for (int i = 0; i < Iq; i++) {
                    gr = fmaf(wiA[i], xv[i], gr);
                    gz = fmaf(wiB[i], xv[i], gz);
                    gn = fmaf(wiC[i], xv[i], gn);
                }
                g[lane] = KRf * gr;
                g[Hq + lane] = KRf * gz;
                g[2 * Hq + lane] = KNf * gn;
                g += Gq;
                xp += Iq;
            }
        }
    }

    // ================= main chunk pipeline =================
    for (int c = 0; c < NCH; c++) {
        __syncthreads();

        if (warp == 0) {
            // -------- recurrence for chunk c --------
            int nst = L - c * CH;
            if (nst > CH) nst = CH;
            uint32_t gxa = gxbase + ((c & 1) * CH * Gq) * 4 + lane * 4;
            uint32_t hrow = hbase + ((c & 1) * CH * HPAD) * 4;
#pragma unroll 1
            for (int s = 0; s < nst; s++) {
                // gate-x inputs first (independent of h)
                float pr = lds32v(gxa);
                float pz = lds32v(gxa + Hq * 4);
                float pn = lds32v(gxa + 2 * Hq * 4);
                // broadcast-load full h (8 x ld.shared.v2.b64)
                u64 hp[16];
#pragma unroll
                for (int j = 0; j < 8; j++) lds128v(hprev + 16 * j, hp[2 * j], hp[2 * j + 1]);

                // 4-way accumulators; gx term folded into acc0 init (off-chain pack)
                u64 ar0 = pk2(pr, 0.f), ar1 = 0ull, ar2 = 0ull, ar3 = 0ull;
                u64 az0 = pk2(pz, 0.f), az1 = 0ull, az2 = 0ull, az3 = 0ull;
                u64 an0 = bhn_pk,       an1 = 0ull, an2 = 0ull, an3 = 0ull;
#pragma unroll
                for (int j = 0; j < 16; j += 4) {
                    ar0 = f2fma(wr[j], hp[j], ar0);
                    an0 = f2fma(wn[j], hp[j], an0);
                    az0 = f2fma(wz[j], hp[j], az0);
                    ar1 = f2fma(wr[j + 1], hp[j + 1], ar1);
                    an1 = f2fma(wn[j + 1], hp[j + 1], an1);
                    az1 = f2fma(wz[j + 1], hp[j + 1], az1);
                    ar2 = f2fma(wr[j + 2], hp[j + 2], ar2);
                    an2 = f2fma(wn[j + 2], hp[j + 2], an2);
                    az2 = f2fma(wz[j + 2], hp[j + 2], az2);
                    ar3 = f2fma(wr[j + 3], hp[j + 3], ar3);
                    an3 = f2fma(wn[j + 3], hp[j + 3], an3);
                    az3 = f2fma(wz[j + 3], hp[j + 3], az3);
                }
                float rs = hsum4(ar0, ar1, ar2, ar3);   // = KR*(gxr+bhr+dot_r)
                float ns = hsum4(an0, an1, an2, an3);   // = KN*(bhn+dot_n)
                float zs = hsum4(az0, az1, az2, az3);   // = KR*(gxz+bhz+dot_z)

                // r = sigmoid(rin) = rcp(1+ex2(rs))
                float r = rcpa(1.0f + ex2a(rs));
                // z path (parallel, off the critical chain)
                float z = rcpa(1.0f + ex2a(zs));
                float omz = 1.0f - z;
                float c0 = fmaf(z, hk, omz);    // omz + z*h
                float c1 = -2.0f * omz;
                // n = tanh(gxn + r*hn) = 1 - 2*q,  q = rcp(1+ex2(fma(r, ns, pn)))
                float q = rcpa(1.0f + ex2a(fmaf(r, ns, pn)));
                // h_new = omz*n + z*h = c0 + c1*q
                hk = fmaf(c1, q, c0);

                sts32v(hrow + lane * 4, hk);
                hprev = hrow;
                __syncwarp();
                hrow += HPAD * 4;
                gxa += Gq * 4;
            }
        } else if (warp == 2) {
            // -------- FC output for chunk c-1 --------
            if (c > 0) {
                const int cp = c - 1;
                const int t = cp * CH + lane;
                float o0 = __ldg(fc_b + 0);
                float o1 = __ldg(fc_b + 1);
                if (t < L) {
                    const float* hr = &s_h[cp & 1][lane][0];
#pragma unroll
                    for (int j = 0; j < Hq; j++) {
                        float hv = hr[j];
                        o0 = fmaf(__ldg(fc_w + j), hv, o0);
                        o1 = fmaf(__ldg(fc_w + Hq + j), hv, o1);
                    }
                }
                float2 v = make_float2(o0, o1);
                *reinterpret_cast<float2*>(out + ((size_t)b * Tq + t) * Oq) = v;
            }
        } else {
            // -------- produce gx for chunk c+1 --------
            const int cc = c + 1;
            if (cc < NCH) {
                const int s0 = (warp == 3) ? (CH / 2) : 0;
                const float* xp = x + ((size_t)b * Tq + cc * CH + s0) * Iq;
                float* g = &s_gx[cc & 1][s0][0];
#pragma unroll 1
                for (int s = 0; s < CH / 2; s++) {
                    float xv[Iq];
#pragma unroll
                    for (int i = 0; i < Iq; i++) xv[i] = xp[i];
                    float gr = biA, gz = biB, gn = biC;
#pragma unroll
                    for (int i = 0; i < Iq; i++) {
                        gr = fmaf(wiA[i], xv[i], gr);
                        gz = fmaf(wiB[i], xv[i], gz);
                        gn = fmaf(wiC[i], xv[i], gn);
                    }
                    g[lane] = KRf * gr;
                    g[Hq + lane] = KRf * gz;
                    g[2 * Hq + lane] = KNf * gn;
                    g += Gq;
                    xp += Iq;
                }
            }
        }
    }

    // ---- epilogue: output last chunk ----
    __syncthreads();
    if (warp == 2) {
        const int cp = NCH - 1;
        const int t = cp * CH + lane;
        float o0 = __ldg(fc_b + 0);
        float o1 = __ldg(fc_b + 1);
        if (t < L) {
            const float* hr = &s_h[cp & 1][lane][0];
#pragma unroll
            for (int j = 0; j < Hq; j++) {
                float hv = hr[j];
                o0 = fmaf(__ldg(fc_w + j), hv, o0);
                o1 = fmaf(__ldg(fc_w + Hq + j), hv, o1);
            }
        }
        float2 v = make_float2(o0, o1);
        *reinterpret_cast<float2*>(out + ((size_t)b * Tq + t) * Oq) = v;
    }
}

extern "C" void kernel_launch(void* const* d_in, const int* in_sizes, int n_in,
                              void* d_out, int out_size) {
    const float* x       = (const float*)d_in[0];
    const int*   lengths = (const int*)d_in[1];
    const float* w_ih    = (const float*)d_in[2];
    const float* w_hh    = (const float*)d_in[3];
    const float* b_ih    = (const float*)d_in[4];
    const float* b_hh    = (const float*)d_in[5];
    const float* fc_w    = (const float*)d_in[6];
    const float* fc_b    = (const float*)d_in[7];
    float* out = (float*)d_out;

    gru_seq_kernel<<<Bq, 128>>>(x, lengths, w_ih, w_hh, b_ih, b_hh, fc_w, fc_b, out);
}